// round 3
// baseline (speedup 1.0000x reference)
#include <cuda_runtime.h>
#include <cstdint>

// ---------------------------------------------------------------------------
// LayerNormDenseGeneral: out = LN(x) @ (kernel + lora_a@lora_b) + bias
// M=8192, K=H=4096, N=F=4096, R=32
// compute_103 build (no tcgen05) => mma.sync tf32 + cp.async pipeline.
// R2 change: K-permuted gmem scratch so mma fragments load as LDS.64
// (half the shared-load issue count of R1's scalar LDS.32).
// pi(t) = (t>>3)*8 + (t&3)*2 + ((t>>2)&1)  within each 32-elt K chunk.
// ---------------------------------------------------------------------------

#define H_DIM 4096
#define F_DIM 4096
#define M_DIM 8192

#define BM 256
#define BN 128
#define BK 32
#define NSTAGE 4
#define NCHUNK (H_DIM / BK)                 // 128
#define A_STAGE_BYTES (BM * BK * 4)         // 32768
#define B_STAGE_BYTES (BN * BK * 4)         // 16384
#define STAGE_BYTES (A_STAGE_BYTES + B_STAGE_BYTES)  // 49152
#define GEMM_SMEM (NSTAGE * STAGE_BYTES)    // 196608

__device__ float g_Y[(size_t)M_DIM * H_DIM];   // LN(x), tf32, K-permuted
__device__ float g_WT[(size_t)F_DIM * H_DIM];  // W_eff^T, tf32, K-permuted

// ---------------------------------------------------------------------------
__device__ __forceinline__ uint32_t smem_u32(const void* p) {
    uint32_t a;
    asm("{ .reg .u64 t; cvta.to.shared.u64 t, %1; cvt.u32.u64 %0, t; }"
        : "=r"(a) : "l"(p));
    return a;
}

__device__ __forceinline__ float tf32r(float x) {
    uint32_t u;
    asm("cvt.rna.tf32.f32 %0, %1;" : "=r"(u) : "f"(x));
    return __uint_as_float(u);
}

__device__ __forceinline__ void cp16(uint32_t dst, const float* src) {
    uint64_t g = __cvta_generic_to_global((const void*)src);
    asm volatile("cp.async.cg.shared.global [%0], [%1], 16;"
                 :: "r"(dst), "l"(g) : "memory");
}

__device__ __forceinline__ uint2 lds64(uint32_t addr) {
    uint2 v;
    asm volatile("ld.shared.v2.b32 {%0,%1}, [%2];"
                 : "=r"(v.x), "=r"(v.y) : "r"(addr));
    return v;
}

__device__ __forceinline__ void mma_tf32(float* d,
                                         uint32_t a0, uint32_t a1,
                                         uint32_t a2, uint32_t a3,
                                         uint32_t b0, uint32_t b1) {
    asm volatile(
        "mma.sync.aligned.m16n8k8.row.col.f32.tf32.tf32.f32 "
        "{%0,%1,%2,%3}, {%4,%5,%6,%7}, {%8,%9}, {%0,%1,%2,%3};"
        : "+f"(d[0]), "+f"(d[1]), "+f"(d[2]), "+f"(d[3])
        : "r"(a0), "r"(a1), "r"(a2), "r"(a3), "r"(b0), "r"(b1));
}

// pi within a 32-elt chunk: word for k-in-chunk t
__device__ __forceinline__ int kperm(int t) {
    return ((t >> 3) << 3) + ((t & 3) << 1) + ((t >> 2) & 1);
}

// ---------------------------------------------------------------------------
// Kernel 1: LayerNorm rows of x -> g_Y (tf32-rounded, K-permuted)
// ---------------------------------------------------------------------------
__global__ __launch_bounds__(256, 1)
void ln_kernel(const float* __restrict__ x, const float* __restrict__ gamma,
               const float* __restrict__ beta) {
    __shared__ float sm[8];
    int row = blockIdx.x;
    const float4* xr = reinterpret_cast<const float4*>(x) + (size_t)row * (H_DIM / 4);
    float4 v[4];
    float s = 0.f;
#pragma unroll
    for (int i = 0; i < 4; i++) {
        v[i] = xr[threadIdx.x + i * 256];
        s += (v[i].x + v[i].y) + (v[i].z + v[i].w);
    }
#pragma unroll
    for (int o = 16; o > 0; o >>= 1) s += __shfl_xor_sync(0xffffffffu, s, o);
    if ((threadIdx.x & 31) == 0) sm[threadIdx.x >> 5] = s;
    __syncthreads();
    float tot = 0.f;
#pragma unroll
    for (int k = 0; k < 8; k++) tot += sm[k];
    float mean = tot * (1.0f / H_DIM);
    __syncthreads();

    float s2 = 0.f;
#pragma unroll
    for (int i = 0; i < 4; i++) {
        float a = v[i].x - mean, b = v[i].y - mean;
        float c = v[i].z - mean, d = v[i].w - mean;
        s2 += (a * a + b * b) + (c * c + d * d);
    }
#pragma unroll
    for (int o = 16; o > 0; o >>= 1) s2 += __shfl_xor_sync(0xffffffffu, s2, o);
    if ((threadIdx.x & 31) == 0) sm[threadIdx.x >> 5] = s2;
    __syncthreads();
    float t2 = 0.f;
#pragma unroll
    for (int k = 0; k < 8; k++) t2 += sm[k];
    float rstd = rsqrtf(t2 * (1.0f / H_DIM) + 1e-6f);

    const float4* g4 = reinterpret_cast<const float4*>(gamma);
    const float4* b4 = reinterpret_cast<const float4*>(beta);
    float* yr = g_Y + (size_t)row * H_DIM;
#pragma unroll
    for (int i = 0; i < 4; i++) {
        int idx = threadIdx.x + i * 256;
        float4 g = g4[idx], bb = b4[idx];
        float o0 = tf32r((v[i].x - mean) * rstd * g.x + bb.x);
        float o1 = tf32r((v[i].y - mean) * rstd * g.y + bb.y);
        float o2 = tf32r((v[i].z - mean) * rstd * g.z + bb.z);
        float o3 = tf32r((v[i].w - mean) * rstd * g.w + bb.w);
        int k0 = idx * 4;
        int base = k0 & ~31;
        int t = k0 & 31;                         // multiple of 4
        int w = base + ((t >> 3) << 3) + ((t >> 2) & 1);
        yr[w + 0] = o0;                          // l3 = 0..3 -> +2 per element
        yr[w + 2] = o1;
        yr[w + 4] = o2;
        yr[w + 6] = o3;
    }
}

// ---------------------------------------------------------------------------
// Kernel 2: g_WT[f][pi(h)] = tf32( kernel[h][f] + lora_a[h][:]@lora_b[:][f] )
// ---------------------------------------------------------------------------
__global__ __launch_bounds__(256, 1)
void weff_kernel(const float* __restrict__ Wk, const float* __restrict__ La,
                 const float* __restrict__ Lb) {
    __shared__ float s_k[32][33], s_a[32][33], s_b[32][33], s_o[32][33];
    int tx = threadIdx.x, ty = threadIdx.y;
    int f0 = blockIdx.x * 32, h0 = blockIdx.y * 32;
#pragma unroll
    for (int r = ty; r < 32; r += 8) {
        s_k[r][tx] = Wk[(size_t)(h0 + r) * F_DIM + f0 + tx];
        s_b[r][tx] = Lb[(size_t)r * F_DIM + f0 + tx];
        s_a[r][tx] = La[(size_t)(h0 + r) * 32 + tx];
    }
    __syncthreads();
#pragma unroll
    for (int hh = ty; hh < 32; hh += 8) {
        float acc = s_k[hh][tx];
#pragma unroll
        for (int r = 0; r < 32; r++) acc += s_a[hh][r] * s_b[r][tx];
        s_o[hh][tx] = acc;
    }
    __syncthreads();
    // h0 is a multiple of 32, so the permutation acts within this tile's h range
#pragma unroll
    for (int ff = ty; ff < 32; ff += 8) {
        int w = h0 + kperm(tx);
        g_WT[(size_t)(f0 + ff) * H_DIM + w] = tf32r(s_o[tx][ff]);
    }
}

// ---------------------------------------------------------------------------
// Kernel 3: tf32 mma.sync GEMM with LDS.64 fragment loads.
// CTA 256x128, warps 4(M)x2(N), warp tile 64x64, BK=32, 4-stage cp.async.
// Smem: row-major 128B rows (K already permuted in gmem),
// 16B-chunk XOR swizzle: byte ^= (row&3)<<5.
// ---------------------------------------------------------------------------
__global__ __launch_bounds__(256, 1)
void gemm_kernel(const float* __restrict__ bias, float* __restrict__ out) {
    extern __shared__ char smem[];
    const uint32_t sb = smem_u32(smem);
    const int tid = threadIdx.x;
    const int wid = tid >> 5, lane = tid & 31;
    const int l2 = lane >> 2, l3 = lane & 3;
    const int mwarp = (wid >> 1) * 64;
    const int nwarp = (wid & 1) * 64;
    const uint32_t swz = (uint32_t)(l2 & 3) << 5;   // row&3 == l2&3 for all frags

    const int mt = blockIdx.x & 31;           // M fast => A reuse within wave
    const int nt = blockIdx.x >> 5;
    const size_t m0 = (size_t)mt * BM, n0 = (size_t)nt * BN;
    const float* Ap = g_Y + m0 * H_DIM;
    const float* Bp = g_WT + n0 * H_DIM;

    auto load_chunk = [&](int j, int stage) {
        const uint32_t st = sb + stage * STAGE_BYTES;
        const float* a = Ap + j * BK;
#pragma unroll
        for (int i = 0; i < 8; i++) {
            int g = tid + i * 256;
            int row = g >> 3, c = g & 7;
            uint32_t off = (uint32_t)row * 128 +
                           (((uint32_t)c * 16) ^ (((uint32_t)row & 3) << 5));
            cp16(st + off, a + (size_t)row * H_DIM + c * 4);
        }
        const float* b = Bp + j * BK;
        const uint32_t stb = st + A_STAGE_BYTES;
#pragma unroll
        for (int i = 0; i < 4; i++) {
            int g = tid + i * 256;
            int row = g >> 3, c = g & 7;
            uint32_t off = (uint32_t)row * 128 +
                           (((uint32_t)c * 16) ^ (((uint32_t)row & 3) << 5));
            cp16(stb + off, b + (size_t)row * H_DIM + c * 4);
        }
        asm volatile("cp.async.commit_group;" ::: "memory");
    };

    float acc[4][8][4];
#pragma unroll
    for (int mi = 0; mi < 4; mi++)
#pragma unroll
        for (int ni = 0; ni < 8; ni++)
#pragma unroll
            for (int q = 0; q < 4; q++) acc[mi][ni][q] = 0.f;

    load_chunk(0, 0);
    load_chunk(1, 1);
    load_chunk(2, 2);

    // per-thread constant pieces of fragment addresses
    const uint32_t aRow0 = (uint32_t)(mwarp + l2) * 128;
    const uint32_t bRow0 = (uint32_t)(nwarp + l2) * 128;

    for (int j = 0; j < NCHUNK; j++) {
        const int stage = j & 3;
        asm volatile("cp.async.wait_group 2;" ::: "memory");
        __syncthreads();

        if (j + 3 < NCHUNK) load_chunk(j + 3, (j + 3) & 3);
        else asm volatile("cp.async.commit_group;" ::: "memory");

        const uint32_t stA = sb + stage * STAGE_BYTES;
        const uint32_t stB = stA + A_STAGE_BYTES;
#pragma unroll
        for (int ks = 0; ks < 4; ks++) {
            const uint32_t koff = (((uint32_t)ks * 32 + (uint32_t)l3 * 8) ^ swz);
            uint2 apr0[4], apr1[4];
#pragma unroll
            for (int mi = 0; mi < 4; mi++) {
                uint32_t ra = stA + aRow0 + (uint32_t)mi * 2048 + koff;
                apr0[mi] = lds64(ra);            // (a0, a2) rows r
                apr1[mi] = lds64(ra + 1024);     // (a1, a3) rows r+8
            }
            uint2 bpr[8];
#pragma unroll
            for (int ni = 0; ni < 8; ni++)
                bpr[ni] = lds64(stB + bRow0 + (uint32_t)ni * 1024 + koff);
#pragma unroll
            for (int mi = 0; mi < 4; mi++)
#pragma unroll
                for (int ni = 0; ni < 8; ni++)
                    mma_tf32(acc[mi][ni],
                             apr0[mi].x, apr1[mi].x, apr0[mi].y, apr1[mi].y,
                             bpr[ni].x, bpr[ni].y);
        }
    }

    // ---- epilogue: direct gmem stores, 32B-aligned float2 segments ----
    const float* bptr = bias + n0 + nwarp + 2 * l3;
#pragma unroll
    for (int ni = 0; ni < 8; ni++) {
        float b0 = __ldg(bptr + ni * 8);
        float b1 = __ldg(bptr + ni * 8 + 1);
        size_t gn = n0 + nwarp + (size_t)ni * 8 + 2 * l3;
#pragma unroll
        for (int mi = 0; mi < 4; mi++) {
            size_t gm = m0 + mwarp + (size_t)mi * 16 + l2;
            float2 v0 = make_float2(acc[mi][ni][0] + b0, acc[mi][ni][1] + b1);
            float2 v1 = make_float2(acc[mi][ni][2] + b0, acc[mi][ni][3] + b1);
            *reinterpret_cast<float2*>(out + gm * F_DIM + gn) = v0;
            *reinterpret_cast<float2*>(out + (gm + 8) * F_DIM + gn) = v1;
        }
    }
}

// ---------------------------------------------------------------------------
extern "C" void kernel_launch(void* const* d_in, const int* in_sizes, int n_in,
                              void* d_out, int out_size) {
    (void)in_sizes; (void)n_in; (void)out_size;
    const float* x       = (const float*)d_in[0];
    const float* scale   = (const float*)d_in[1];
    const float* ln_bias = (const float*)d_in[2];
    const float* kern    = (const float*)d_in[3];
    const float* la      = (const float*)d_in[4];
    const float* lb      = (const float*)d_in[5];
    const float* bias    = (const float*)d_in[6];
    float* out = (float*)d_out;

    cudaFuncSetAttribute(gemm_kernel,
                         cudaFuncAttributeMaxDynamicSharedMemorySize, GEMM_SMEM);

    ln_kernel<<<M_DIM, 256>>>(x, scale, ln_bias);
    weff_kernel<<<dim3(F_DIM / 32, H_DIM / 32), dim3(32, 8)>>>(kern, la, lb);
    gemm_kernel<<<(M_DIM / BM) * (F_DIM / BN), 256, GEMM_SMEM>>>(bias, out);
}

// round 4
// speedup vs baseline: 1.8417x; 1.8417x over previous
#include <cuda_runtime.h>
#include <cuda_fp16.h>
#include <cstdint>

// ---------------------------------------------------------------------------
// LayerNormDenseGeneral: out = LN(x) @ (kernel + lora_a@lora_b) + bias
// M=8192, K=H=4096, N=F=4096, R=32
// compute_103 build (no tcgen05). R4: fp16 mma.sync m16n8k16 (same 10-bit
// mantissa as tf32, half the HMMA instruction count, half the memory traffic).
// ---------------------------------------------------------------------------

#define H_DIM 4096
#define F_DIM 4096
#define M_DIM 8192

#define BM 256
#define BN 128
#define BK 64                                // K elements per chunk (128 B fp16)
#define NCHUNK (H_DIM / BK)                  // 64
#define A_STAGE_BYTES (BM * BK * 2)          // 32768
#define B_STAGE_BYTES (BN * BK * 2)          // 16384
#define STAGE_BYTES (A_STAGE_BYTES + B_STAGE_BYTES)   // 49152
#define GEMM_SMEM (4 * STAGE_BYTES)          // 196608

__device__ __align__(16) __half g_Y[(size_t)M_DIM * H_DIM];   // LN(x), fp16
__device__ __align__(16) __half g_WT[(size_t)F_DIM * H_DIM];  // W_eff^T, fp16

// ---------------------------------------------------------------------------
__device__ __forceinline__ uint32_t smem_u32(const void* p) {
    uint32_t a;
    asm("{ .reg .u64 t; cvta.to.shared.u64 t, %1; cvt.u32.u64 %0, t; }"
        : "=r"(a) : "l"(p));
    return a;
}

__device__ __forceinline__ void cp16(uint32_t dst, const void* src) {
    uint64_t g = __cvta_generic_to_global(src);
    asm volatile("cp.async.cg.shared.global [%0], [%1], 16;"
                 :: "r"(dst), "l"(g) : "memory");
}

__device__ __forceinline__ uint32_t lds32(uint32_t addr) {
    uint32_t v;
    asm volatile("ld.shared.b32 %0, [%1];" : "=r"(v) : "r"(addr));
    return v;
}

__device__ __forceinline__ uint32_t packh2(float lo, float hi) {
    __half2 h = __floats2half2_rn(lo, hi);
    return *reinterpret_cast<uint32_t*>(&h);
}

__device__ __forceinline__ void mma_f16(float* d,
                                        uint32_t a0, uint32_t a1,
                                        uint32_t a2, uint32_t a3,
                                        uint32_t b0, uint32_t b1) {
    asm volatile(
        "mma.sync.aligned.m16n8k16.row.col.f32.f16.f16.f32 "
        "{%0,%1,%2,%3}, {%4,%5,%6,%7}, {%8,%9}, {%0,%1,%2,%3};"
        : "+f"(d[0]), "+f"(d[1]), "+f"(d[2]), "+f"(d[3])
        : "r"(a0), "r"(a1), "r"(a2), "r"(a3), "r"(b0), "r"(b1));
}

// ---------------------------------------------------------------------------
// Kernel 1: LayerNorm rows of x -> g_Y (fp16)
// ---------------------------------------------------------------------------
__global__ __launch_bounds__(256, 1)
void ln_kernel(const float* __restrict__ x, const float* __restrict__ gamma,
               const float* __restrict__ beta) {
    __shared__ float sm[8];
    int row = blockIdx.x;
    const float4* xr = reinterpret_cast<const float4*>(x) + (size_t)row * (H_DIM / 4);
    float4 v[4];
    float s = 0.f;
#pragma unroll
    for (int i = 0; i < 4; i++) {
        v[i] = xr[threadIdx.x + i * 256];
        s += (v[i].x + v[i].y) + (v[i].z + v[i].w);
    }
#pragma unroll
    for (int o = 16; o > 0; o >>= 1) s += __shfl_xor_sync(0xffffffffu, s, o);
    if ((threadIdx.x & 31) == 0) sm[threadIdx.x >> 5] = s;
    __syncthreads();
    float tot = 0.f;
#pragma unroll
    for (int k = 0; k < 8; k++) tot += sm[k];
    float mean = tot * (1.0f / H_DIM);
    __syncthreads();

    float s2 = 0.f;
#pragma unroll
    for (int i = 0; i < 4; i++) {
        float a = v[i].x - mean, b = v[i].y - mean;
        float c = v[i].z - mean, d = v[i].w - mean;
        s2 += (a * a + b * b) + (c * c + d * d);
    }
#pragma unroll
    for (int o = 16; o > 0; o >>= 1) s2 += __shfl_xor_sync(0xffffffffu, s2, o);
    if ((threadIdx.x & 31) == 0) sm[threadIdx.x >> 5] = s2;
    __syncthreads();
    float t2 = 0.f;
#pragma unroll
    for (int k = 0; k < 8; k++) t2 += sm[k];
    float rstd = rsqrtf(t2 * (1.0f / H_DIM) + 1e-6f);

    const float4* g4 = reinterpret_cast<const float4*>(gamma);
    const float4* b4 = reinterpret_cast<const float4*>(beta);
    uint2* yr = reinterpret_cast<uint2*>(g_Y + (size_t)row * H_DIM);
#pragma unroll
    for (int i = 0; i < 4; i++) {
        int idx = threadIdx.x + i * 256;
        float4 g = g4[idx], bb = b4[idx];
        float o0 = (v[i].x - mean) * rstd * g.x + bb.x;
        float o1 = (v[i].y - mean) * rstd * g.y + bb.y;
        float o2 = (v[i].z - mean) * rstd * g.z + bb.z;
        float o3 = (v[i].w - mean) * rstd * g.w + bb.w;
        yr[idx] = make_uint2(packh2(o0, o1), packh2(o2, o3));
    }
}

// ---------------------------------------------------------------------------
// Kernel 2: g_WT[f][h] = fp16( kernel[h][f] + lora_a[h][:]@lora_b[:][f] )
// 32x32 tile transpose so GEMM B operand is [N][K] K-major.
// ---------------------------------------------------------------------------
__global__ __launch_bounds__(256, 1)
void weff_kernel(const float* __restrict__ Wk, const float* __restrict__ La,
                 const float* __restrict__ Lb) {
    __shared__ float s_k[32][33], s_a[32][33], s_b[32][33], s_o[32][33];
    int tx = threadIdx.x, ty = threadIdx.y;
    int f0 = blockIdx.x * 32, h0 = blockIdx.y * 32;
#pragma unroll
    for (int r = ty; r < 32; r += 8) {
        s_k[r][tx] = Wk[(size_t)(h0 + r) * F_DIM + f0 + tx];
        s_b[r][tx] = Lb[(size_t)r * F_DIM + f0 + tx];
        s_a[r][tx] = La[(size_t)(h0 + r) * 32 + tx];
    }
    __syncthreads();
#pragma unroll
    for (int hh = ty; hh < 32; hh += 8) {
        float acc = s_k[hh][tx];
#pragma unroll
        for (int r = 0; r < 32; r++) acc += s_a[hh][r] * s_b[r][tx];
        s_o[hh][tx] = acc;
    }
    __syncthreads();
#pragma unroll
    for (int ff = ty; ff < 32; ff += 8) {
        g_WT[(size_t)(f0 + ff) * H_DIM + h0 + tx] = __float2half_rn(s_o[tx][ff]);
    }
}

// ---------------------------------------------------------------------------
// Kernel 3: fp16 mma.sync GEMM. out[m][n] = sum_k Y[m][k]*WT[n][k] + bias[n]
// CTA 256x128, warps 4(M)x2(N), warp tile 64x64, BK=64 (128 B fp16 rows),
// 4-stage cp.async. Swizzle: byte ^ ((row&7)<<4), conflict-free for both
// 16B cp.async stores and fragment lds.32 reads.
// ---------------------------------------------------------------------------
__global__ __launch_bounds__(256, 1)
void gemm_kernel(const float* __restrict__ bias, float* __restrict__ out) {
    extern __shared__ char smem[];
    const uint32_t sb = smem_u32(smem);
    const int tid = threadIdx.x;
    const int wid = tid >> 5, lane = tid & 31;
    const int l2 = lane >> 2, l3 = lane & 3;
    const int mwarp = (wid >> 1) * 64;
    const int nwarp = (wid & 1) * 64;
    const uint32_t swz = (uint32_t)(l2 & 7) << 4;

    const int mt = blockIdx.x & 31;           // M fast => A reuse within wave
    const int nt = blockIdx.x >> 5;
    const size_t m0 = (size_t)mt * BM, n0 = (size_t)nt * BN;
    const __half* Ap = g_Y + m0 * H_DIM;
    const __half* Bp = g_WT + n0 * H_DIM;

    auto load_chunk = [&](int j, int stage) {
        const uint32_t st = sb + stage * STAGE_BYTES;
        const __half* a = Ap + j * BK;
#pragma unroll
        for (int i = 0; i < 8; i++) {
            int g = tid + i * 256;
            int row = g >> 3, c = g & 7;
            uint32_t off = (uint32_t)row * 128 +
                           (((uint32_t)c * 16) ^ (((uint32_t)row & 7) << 4));
            cp16(st + off, a + (size_t)row * H_DIM + c * 8);
        }
        const __half* b = Bp + j * BK;
        const uint32_t stb = st + A_STAGE_BYTES;
#pragma unroll
        for (int i = 0; i < 4; i++) {
            int g = tid + i * 256;
            int row = g >> 3, c = g & 7;
            uint32_t off = (uint32_t)row * 128 +
                           (((uint32_t)c * 16) ^ (((uint32_t)row & 7) << 4));
            cp16(stb + off, b + (size_t)row * H_DIM + c * 8);
        }
        asm volatile("cp.async.commit_group;" ::: "memory");
    };

    float acc[4][8][4];
#pragma unroll
    for (int mi = 0; mi < 4; mi++)
#pragma unroll
        for (int ni = 0; ni < 8; ni++)
#pragma unroll
            for (int q = 0; q < 4; q++) acc[mi][ni][q] = 0.f;

    load_chunk(0, 0);
    load_chunk(1, 1);
    load_chunk(2, 2);

    const uint32_t aRow0 = (uint32_t)(mwarp + l2) * 128;
    const uint32_t bRow0 = (uint32_t)(nwarp + l2) * 128;

    for (int j = 0; j < NCHUNK; j++) {
        const int stage = j & 3;
        asm volatile("cp.async.wait_group 2;" ::: "memory");
        __syncthreads();

        if (j + 3 < NCHUNK) load_chunk(j + 3, (j + 3) & 3);
        else asm volatile("cp.async.commit_group;" ::: "memory");

        const uint32_t stA = sb + stage * STAGE_BYTES;
        const uint32_t stB = stA + A_STAGE_BYTES;
#pragma unroll
        for (int ks = 0; ks < 4; ks++) {
            const uint32_t k0 = ((uint32_t)ks * 32 + (uint32_t)l3 * 4) ^ swz;
            const uint32_t k1 = ((uint32_t)ks * 32 + 16 + (uint32_t)l3 * 4) ^ swz;
            uint32_t a0[4], a1[4], a2[4], a3[4];
#pragma unroll
            for (int mi = 0; mi < 4; mi++) {
                uint32_t ra = stA + aRow0 + (uint32_t)mi * 2048;
                a0[mi] = lds32(ra + k0);
                a2[mi] = lds32(ra + k1);
                a1[mi] = lds32(ra + 1024 + k0);
                a3[mi] = lds32(ra + 1024 + k1);
            }
            uint32_t b0[8], b1[8];
#pragma unroll
            for (int ni = 0; ni < 8; ni++) {
                uint32_t rb = stB + bRow0 + (uint32_t)ni * 1024;
                b0[ni] = lds32(rb + k0);
                b1[ni] = lds32(rb + k1);
            }
#pragma unroll
            for (int mi = 0; mi < 4; mi++)
#pragma unroll
                for (int ni = 0; ni < 8; ni++)
                    mma_f16(acc[mi][ni], a0[mi], a1[mi], a2[mi], a3[mi],
                            b0[ni], b1[ni]);
        }
    }

    // ---- epilogue: direct gmem stores, 32B-aligned float2 segments ----
    const float* bptr = bias + n0 + nwarp + 2 * l3;
#pragma unroll
    for (int ni = 0; ni < 8; ni++) {
        float bv0 = __ldg(bptr + ni * 8);
        float bv1 = __ldg(bptr + ni * 8 + 1);
        size_t gn = n0 + nwarp + (size_t)ni * 8 + 2 * l3;
#pragma unroll
        for (int mi = 0; mi < 4; mi++) {
            size_t gm = m0 + mwarp + (size_t)mi * 16 + l2;
            float2 v0 = make_float2(acc[mi][ni][0] + bv0, acc[mi][ni][1] + bv1);
            float2 v1 = make_float2(acc[mi][ni][2] + bv0, acc[mi][ni][3] + bv1);
            *reinterpret_cast<float2*>(out + gm * F_DIM + gn) = v0;
            *reinterpret_cast<float2*>(out + (gm + 8) * F_DIM + gn) = v1;
        }
    }
}

// ---------------------------------------------------------------------------
extern "C" void kernel_launch(void* const* d_in, const int* in_sizes, int n_in,
                              void* d_out, int out_size) {
    (void)in_sizes; (void)n_in; (void)out_size;
    const float* x       = (const float*)d_in[0];
    const float* scale   = (const float*)d_in[1];
    const float* ln_bias = (const float*)d_in[2];
    const float* kern    = (const float*)d_in[3];
    const float* la      = (const float*)d_in[4];
    const float* lb      = (const float*)d_in[5];
    const float* bias    = (const float*)d_in[6];
    float* out = (float*)d_out;

    cudaFuncSetAttribute(gemm_kernel,
                         cudaFuncAttributeMaxDynamicSharedMemorySize, GEMM_SMEM);

    ln_kernel<<<M_DIM, 256>>>(x, scale, ln_bias);
    weff_kernel<<<dim3(F_DIM / 32, H_DIM / 32), dim3(32, 8)>>>(kern, la, lb);
    gemm_kernel<<<(M_DIM / BM) * (F_DIM / BN), 256, GEMM_SMEM>>>(bias, out);
}

// round 5
// speedup vs baseline: 1.8935x; 1.0281x over previous
#include <cuda_runtime.h>
#include <cuda_fp16.h>
#include <cstdint>

// ---------------------------------------------------------------------------
// LayerNormDenseGeneral: out = LN(x) @ (kernel + lora_a@lora_b) + bias
// M=8192, K=H=4096, N=F=4096, R=32
// compute_103 build (no tcgen05). fp16 mma.sync m16n8k16.
// R5: ldmatrix.x4 fragment loads (1 LDSM replaces 8 LDS.32) to strip the
// shared-load issue stream off the HMMA pipe.
// ---------------------------------------------------------------------------

#define H_DIM 4096
#define F_DIM 4096
#define M_DIM 8192

#define BM 256
#define BN 128
#define BK 64                                // K elements per chunk (128 B fp16)
#define NCHUNK (H_DIM / BK)                  // 64
#define A_STAGE_BYTES (BM * BK * 2)          // 32768
#define B_STAGE_BYTES (BN * BK * 2)          // 16384
#define STAGE_BYTES (A_STAGE_BYTES + B_STAGE_BYTES)   // 49152
#define GEMM_SMEM (4 * STAGE_BYTES)          // 196608

__device__ __align__(16) __half g_Y[(size_t)M_DIM * H_DIM];   // LN(x), fp16
__device__ __align__(16) __half g_WT[(size_t)F_DIM * H_DIM];  // W_eff^T, fp16

// ---------------------------------------------------------------------------
__device__ __forceinline__ uint32_t smem_u32(const void* p) {
    uint32_t a;
    asm("{ .reg .u64 t; cvta.to.shared.u64 t, %1; cvt.u32.u64 %0, t; }"
        : "=r"(a) : "l"(p));
    return a;
}

__device__ __forceinline__ void cp16(uint32_t dst, const void* src) {
    uint64_t g = __cvta_generic_to_global(src);
    asm volatile("cp.async.cg.shared.global [%0], [%1], 16;"
                 :: "r"(dst), "l"(g) : "memory");
}

__device__ __forceinline__ void ldsm_x4(uint32_t* r, uint32_t addr) {
    asm volatile("ldmatrix.sync.aligned.m8n8.x4.shared.b16 {%0,%1,%2,%3}, [%4];"
                 : "=r"(r[0]), "=r"(r[1]), "=r"(r[2]), "=r"(r[3]) : "r"(addr));
}

__device__ __forceinline__ uint32_t packh2(float lo, float hi) {
    __half2 h = __floats2half2_rn(lo, hi);
    return *reinterpret_cast<uint32_t*>(&h);
}

__device__ __forceinline__ void mma_f16(float* d,
                                        uint32_t a0, uint32_t a1,
                                        uint32_t a2, uint32_t a3,
                                        uint32_t b0, uint32_t b1) {
    asm volatile(
        "mma.sync.aligned.m16n8k16.row.col.f32.f16.f16.f32 "
        "{%0,%1,%2,%3}, {%4,%5,%6,%7}, {%8,%9}, {%0,%1,%2,%3};"
        : "+f"(d[0]), "+f"(d[1]), "+f"(d[2]), "+f"(d[3])
        : "r"(a0), "r"(a1), "r"(a2), "r"(a3), "r"(b0), "r"(b1));
}

// ---------------------------------------------------------------------------
// Kernel 1: LayerNorm rows of x -> g_Y (fp16)
// ---------------------------------------------------------------------------
__global__ __launch_bounds__(256, 1)
void ln_kernel(const float* __restrict__ x, const float* __restrict__ gamma,
               const float* __restrict__ beta) {
    __shared__ float sm[8];
    int row = blockIdx.x;
    const float4* xr = reinterpret_cast<const float4*>(x) + (size_t)row * (H_DIM / 4);
    float4 v[4];
    float s = 0.f;
#pragma unroll
    for (int i = 0; i < 4; i++) {
        v[i] = xr[threadIdx.x + i * 256];
        s += (v[i].x + v[i].y) + (v[i].z + v[i].w);
    }
#pragma unroll
    for (int o = 16; o > 0; o >>= 1) s += __shfl_xor_sync(0xffffffffu, s, o);
    if ((threadIdx.x & 31) == 0) sm[threadIdx.x >> 5] = s;
    __syncthreads();
    float tot = 0.f;
#pragma unroll
    for (int k = 0; k < 8; k++) tot += sm[k];
    float mean = tot * (1.0f / H_DIM);
    __syncthreads();

    float s2 = 0.f;
#pragma unroll
    for (int i = 0; i < 4; i++) {
        float a = v[i].x - mean, b = v[i].y - mean;
        float c = v[i].z - mean, d = v[i].w - mean;
        s2 += (a * a + b * b) + (c * c + d * d);
    }
#pragma unroll
    for (int o = 16; o > 0; o >>= 1) s2 += __shfl_xor_sync(0xffffffffu, s2, o);
    if ((threadIdx.x & 31) == 0) sm[threadIdx.x >> 5] = s2;
    __syncthreads();
    float t2 = 0.f;
#pragma unroll
    for (int k = 0; k < 8; k++) t2 += sm[k];
    float rstd = rsqrtf(t2 * (1.0f / H_DIM) + 1e-6f);

    const float4* g4 = reinterpret_cast<const float4*>(gamma);
    const float4* b4 = reinterpret_cast<const float4*>(beta);
    uint2* yr = reinterpret_cast<uint2*>(g_Y + (size_t)row * H_DIM);
#pragma unroll
    for (int i = 0; i < 4; i++) {
        int idx = threadIdx.x + i * 256;
        float4 g = g4[idx], bb = b4[idx];
        float o0 = (v[i].x - mean) * rstd * g.x + bb.x;
        float o1 = (v[i].y - mean) * rstd * g.y + bb.y;
        float o2 = (v[i].z - mean) * rstd * g.z + bb.z;
        float o3 = (v[i].w - mean) * rstd * g.w + bb.w;
        yr[idx] = make_uint2(packh2(o0, o1), packh2(o2, o3));
    }
}

// ---------------------------------------------------------------------------
// Kernel 2: g_WT[f][h] = fp16( kernel[h][f] + lora_a[h][:]@lora_b[:][f] )
// ---------------------------------------------------------------------------
__global__ __launch_bounds__(256, 1)
void weff_kernel(const float* __restrict__ Wk, const float* __restrict__ La,
                 const float* __restrict__ Lb) {
    __shared__ float s_k[32][33], s_a[32][33], s_b[32][33], s_o[32][33];
    int tx = threadIdx.x, ty = threadIdx.y;
    int f0 = blockIdx.x * 32, h0 = blockIdx.y * 32;
#pragma unroll
    for (int r = ty; r < 32; r += 8) {
        s_k[r][tx] = Wk[(size_t)(h0 + r) * F_DIM + f0 + tx];
        s_b[r][tx] = Lb[(size_t)r * F_DIM + f0 + tx];
        s_a[r][tx] = La[(size_t)(h0 + r) * 32 + tx];
    }
    __syncthreads();
#pragma unroll
    for (int hh = ty; hh < 32; hh += 8) {
        float acc = s_k[hh][tx];
#pragma unroll
        for (int r = 0; r < 32; r++) acc += s_a[hh][r] * s_b[r][tx];
        s_o[hh][tx] = acc;
    }
    __syncthreads();
#pragma unroll
    for (int ff = ty; ff < 32; ff += 8) {
        g_WT[(size_t)(f0 + ff) * H_DIM + h0 + tx] = __float2half_rn(s_o[tx][ff]);
    }
}

// ---------------------------------------------------------------------------
// Kernel 3: fp16 mma.sync GEMM, ldmatrix.x4 fragment loads.
// CTA 256x128, warps 4(M)x2(N), warp tile 64x64, BK=64 (128 B fp16 rows),
// 4-stage cp.async. Swizzle: byte ^ ((row&7)<<4).
// ---------------------------------------------------------------------------
__global__ __launch_bounds__(256, 1)
void gemm_kernel(const float* __restrict__ bias, float* __restrict__ out) {
    extern __shared__ char smem[];
    const uint32_t sb = smem_u32(smem);
    const int tid = threadIdx.x;
    const int wid = tid >> 5, lane = tid & 31;
    const int l2 = lane >> 2, l3 = lane & 3;
    const int mwarp = (wid >> 1) * 64;
    const int nwarp = (wid & 1) * 64;

    const int mt = blockIdx.x & 31;           // M fast => A reuse within wave
    const int nt = blockIdx.x >> 5;
    const size_t m0 = (size_t)mt * BM, n0 = (size_t)nt * BN;
    const __half* Ap = g_Y + m0 * H_DIM;
    const __half* Bp = g_WT + n0 * H_DIM;

    auto load_chunk = [&](int j, int stage) {
        const uint32_t st = sb + stage * STAGE_BYTES;
        const __half* a = Ap + j * BK;
#pragma unroll
        for (int i = 0; i < 8; i++) {
            int g = tid + i * 256;
            int row = g >> 3, c = g & 7;
            uint32_t off = (uint32_t)row * 128 +
                           (((uint32_t)c * 16) ^ (((uint32_t)row & 7) << 4));
            cp16(st + off, a + (size_t)row * H_DIM + c * 8);
        }
        const __half* b = Bp + j * BK;
        const uint32_t stb = st + A_STAGE_BYTES;
#pragma unroll
        for (int i = 0; i < 4; i++) {
            int g = tid + i * 256;
            int row = g >> 3, c = g & 7;
            uint32_t off = (uint32_t)row * 128 +
                           (((uint32_t)c * 16) ^ (((uint32_t)row & 7) << 4));
            cp16(stb + off, b + (size_t)row * H_DIM + c * 8);
        }
        asm volatile("cp.async.commit_group;" ::: "memory");
    };

    float acc[4][8][4];
#pragma unroll
    for (int mi = 0; mi < 4; mi++)
#pragma unroll
        for (int ni = 0; ni < 8; ni++)
#pragma unroll
            for (int q = 0; q < 4; q++) acc[mi][ni][q] = 0.f;

    load_chunk(0, 0);
    load_chunk(1, 1);
    load_chunk(2, 2);

    // ldmatrix lane addressing (swizzle row&7 == lane&7 in both cases)
    // A: rows m = mwarp + mi*16 + (lane&15); k half from lane>>4
    const uint32_t aRowB = (uint32_t)(mwarp + (lane & 15)) * 128;
    const uint32_t aSel  = ((uint32_t)(lane >> 4)) << 4;     // 0 or 16 bytes
    // B: rows n = nwarp + p*16 + (lane&7) + ((lane>>4)<<3); k half from bit3
    const uint32_t bRowB = (uint32_t)(nwarp + (lane & 7) + ((lane >> 4) << 3)) * 128;
    const uint32_t bSel  = ((uint32_t)((lane >> 3) & 1)) << 4;
    const uint32_t swzA  = ((uint32_t)(lane & 7)) << 4;

    for (int j = 0; j < NCHUNK; j++) {
        const int stage = j & 3;
        asm volatile("cp.async.wait_group 2;" ::: "memory");
        __syncthreads();

        if (j + 3 < NCHUNK) load_chunk(j + 3, (j + 3) & 3);
        else asm volatile("cp.async.commit_group;" ::: "memory");

        const uint32_t stA = sb + stage * STAGE_BYTES;
        const uint32_t stB = stA + A_STAGE_BYTES;
#pragma unroll
        for (int ks = 0; ks < 4; ks++) {
            const uint32_t kaoff = (((uint32_t)ks * 32 + aSel) ^ swzA);
            const uint32_t kboff = (((uint32_t)ks * 32 + bSel) ^ swzA);
            uint32_t af[4][4];
#pragma unroll
            for (int mi = 0; mi < 4; mi++)
                ldsm_x4(af[mi], stA + aRowB + (uint32_t)mi * 2048 + kaoff);
            uint32_t bf[4][4];
#pragma unroll
            for (int p = 0; p < 4; p++)
                ldsm_x4(bf[p], stB + bRowB + (uint32_t)p * 2048 + kboff);
#pragma unroll
            for (int mi = 0; mi < 4; mi++)
#pragma unroll
                for (int p = 0; p < 4; p++) {
                    mma_f16(acc[mi][2 * p],     af[mi][0], af[mi][1],
                            af[mi][2], af[mi][3], bf[p][0], bf[p][1]);
                    mma_f16(acc[mi][2 * p + 1], af[mi][0], af[mi][1],
                            af[mi][2], af[mi][3], bf[p][2], bf[p][3]);
                }
        }
    }

    // ---- epilogue: direct gmem stores, 32B-aligned float2 segments ----
    const float* bptr = bias + n0 + nwarp + 2 * l3;
#pragma unroll
    for (int ni = 0; ni < 8; ni++) {
        float bv0 = __ldg(bptr + ni * 8);
        float bv1 = __ldg(bptr + ni * 8 + 1);
        size_t gn = n0 + nwarp + (size_t)ni * 8 + 2 * l3;
#pragma unroll
        for (int mi = 0; mi < 4; mi++) {
            size_t gm = m0 + mwarp + (size_t)mi * 16 + l2;
            float2 v0 = make_float2(acc[mi][ni][0] + bv0, acc[mi][ni][1] + bv1);
            float2 v1 = make_float2(acc[mi][ni][2] + bv0, acc[mi][ni][3] + bv1);
            *reinterpret_cast<float2*>(out + gm * F_DIM + gn) = v0;
            *reinterpret_cast<float2*>(out + (gm + 8) * F_DIM + gn) = v1;
        }
    }
}

// ---------------------------------------------------------------------------
extern "C" void kernel_launch(void* const* d_in, const int* in_sizes, int n_in,
                              void* d_out, int out_size) {
    (void)in_sizes; (void)n_in; (void)out_size;
    const float* x       = (const float*)d_in[0];
    const float* scale   = (const float*)d_in[1];
    const float* ln_bias = (const float*)d_in[2];
    const float* kern    = (const float*)d_in[3];
    const float* la      = (const float*)d_in[4];
    const float* lb      = (const float*)d_in[5];
    const float* bias    = (const float*)d_in[6];
    float* out = (float*)d_out;

    cudaFuncSetAttribute(gemm_kernel,
                         cudaFuncAttributeMaxDynamicSharedMemorySize, GEMM_SMEM);

    ln_kernel<<<M_DIM, 256>>>(x, scale, ln_bias);
    weff_kernel<<<dim3(F_DIM / 32, H_DIM / 32), dim3(32, 8)>>>(kern, la, lb);
    gemm_kernel<<<(M_DIM / BM) * (F_DIM / BN), 256, GEMM_SMEM>>>(bias, out);
}

// round 6
// speedup vs baseline: 1.9813x; 1.0464x over previous
#include <cuda_runtime.h>
#include <cuda_fp16.h>
#include <cstdint>

// ---------------------------------------------------------------------------
// LayerNormDenseGeneral: out = LN(x) @ (kernel + lora_a@lora_b) + bias
// M=8192, K=H=4096, N=F=4096, R=32
// compute_103 build (no tcgen05). fp16 mma.sync m16n8k16 + ldmatrix.x4.
// R6: 512-thread CTA (16 warps, 4x4), warp tile 64x32 -> 4 warps/SMSP to
// fill HMMA pipe bubbles that 2 warps/SMSP could not cover.
// ---------------------------------------------------------------------------

#define H_DIM 4096
#define F_DIM 4096
#define M_DIM 8192

#define BM 256
#define BN 128
#define BK 64                                // K elements per chunk (128 B fp16)
#define NCHUNK (H_DIM / BK)                  // 64
#define A_STAGE_BYTES (BM * BK * 2)          // 32768
#define B_STAGE_BYTES (BN * BK * 2)          // 16384
#define STAGE_BYTES (A_STAGE_BYTES + B_STAGE_BYTES)   // 49152
#define GEMM_SMEM (4 * STAGE_BYTES)          // 196608

__device__ __align__(16) __half g_Y[(size_t)M_DIM * H_DIM];   // LN(x), fp16
__device__ __align__(16) __half g_WT[(size_t)F_DIM * H_DIM];  // W_eff^T, fp16

// ---------------------------------------------------------------------------
__device__ __forceinline__ uint32_t smem_u32(const void* p) {
    uint32_t a;
    asm("{ .reg .u64 t; cvta.to.shared.u64 t, %1; cvt.u32.u64 %0, t; }"
        : "=r"(a) : "l"(p));
    return a;
}

__device__ __forceinline__ void cp16(uint32_t dst, const void* src) {
    uint64_t g = __cvta_generic_to_global(src);
    asm volatile("cp.async.cg.shared.global [%0], [%1], 16;"
                 :: "r"(dst), "l"(g) : "memory");
}

__device__ __forceinline__ void ldsm_x4(uint32_t* r, uint32_t addr) {
    asm volatile("ldmatrix.sync.aligned.m8n8.x4.shared.b16 {%0,%1,%2,%3}, [%4];"
                 : "=r"(r[0]), "=r"(r[1]), "=r"(r[2]), "=r"(r[3]) : "r"(addr));
}

__device__ __forceinline__ uint32_t packh2(float lo, float hi) {
    __half2 h = __floats2half2_rn(lo, hi);
    return *reinterpret_cast<uint32_t*>(&h);
}

__device__ __forceinline__ void mma_f16(float* d,
                                        uint32_t a0, uint32_t a1,
                                        uint32_t a2, uint32_t a3,
                                        uint32_t b0, uint32_t b1) {
    asm volatile(
        "mma.sync.aligned.m16n8k16.row.col.f32.f16.f16.f32 "
        "{%0,%1,%2,%3}, {%4,%5,%6,%7}, {%8,%9}, {%0,%1,%2,%3};"
        : "+f"(d[0]), "+f"(d[1]), "+f"(d[2]), "+f"(d[3])
        : "r"(a0), "r"(a1), "r"(a2), "r"(a3), "r"(b0), "r"(b1));
}

// ---------------------------------------------------------------------------
// Kernel 1: LayerNorm rows of x -> g_Y (fp16)
// ---------------------------------------------------------------------------
__global__ __launch_bounds__(256, 1)
void ln_kernel(const float* __restrict__ x, const float* __restrict__ gamma,
               const float* __restrict__ beta) {
    __shared__ float sm[8];
    int row = blockIdx.x;
    const float4* xr = reinterpret_cast<const float4*>(x) + (size_t)row * (H_DIM / 4);
    float4 v[4];
    float s = 0.f;
#pragma unroll
    for (int i = 0; i < 4; i++) {
        v[i] = xr[threadIdx.x + i * 256];
        s += (v[i].x + v[i].y) + (v[i].z + v[i].w);
    }
#pragma unroll
    for (int o = 16; o > 0; o >>= 1) s += __shfl_xor_sync(0xffffffffu, s, o);
    if ((threadIdx.x & 31) == 0) sm[threadIdx.x >> 5] = s;
    __syncthreads();
    float tot = 0.f;
#pragma unroll
    for (int k = 0; k < 8; k++) tot += sm[k];
    float mean = tot * (1.0f / H_DIM);
    __syncthreads();

    float s2 = 0.f;
#pragma unroll
    for (int i = 0; i < 4; i++) {
        float a = v[i].x - mean, b = v[i].y - mean;
        float c = v[i].z - mean, d = v[i].w - mean;
        s2 += (a * a + b * b) + (c * c + d * d);
    }
#pragma unroll
    for (int o = 16; o > 0; o >>= 1) s2 += __shfl_xor_sync(0xffffffffu, s2, o);
    if ((threadIdx.x & 31) == 0) sm[threadIdx.x >> 5] = s2;
    __syncthreads();
    float t2 = 0.f;
#pragma unroll
    for (int k = 0; k < 8; k++) t2 += sm[k];
    float rstd = rsqrtf(t2 * (1.0f / H_DIM) + 1e-6f);

    const float4* g4 = reinterpret_cast<const float4*>(gamma);
    const float4* b4 = reinterpret_cast<const float4*>(beta);
    uint2* yr = reinterpret_cast<uint2*>(g_Y + (size_t)row * H_DIM);
#pragma unroll
    for (int i = 0; i < 4; i++) {
        int idx = threadIdx.x + i * 256;
        float4 g = g4[idx], bb = b4[idx];
        float o0 = (v[i].x - mean) * rstd * g.x + bb.x;
        float o1 = (v[i].y - mean) * rstd * g.y + bb.y;
        float o2 = (v[i].z - mean) * rstd * g.z + bb.z;
        float o3 = (v[i].w - mean) * rstd * g.w + bb.w;
        yr[idx] = make_uint2(packh2(o0, o1), packh2(o2, o3));
    }
}

// ---------------------------------------------------------------------------
// Kernel 2: g_WT[f][h] = fp16( kernel[h][f] + lora_a[h][:]@lora_b[:][f] )
// ---------------------------------------------------------------------------
__global__ __launch_bounds__(256, 1)
void weff_kernel(const float* __restrict__ Wk, const float* __restrict__ La,
                 const float* __restrict__ Lb) {
    __shared__ float s_k[32][33], s_a[32][33], s_b[32][33], s_o[32][33];
    int tx = threadIdx.x, ty = threadIdx.y;
    int f0 = blockIdx.x * 32, h0 = blockIdx.y * 32;
#pragma unroll
    for (int r = ty; r < 32; r += 8) {
        s_k[r][tx] = Wk[(size_t)(h0 + r) * F_DIM + f0 + tx];
        s_b[r][tx] = Lb[(size_t)r * F_DIM + f0 + tx];
        s_a[r][tx] = La[(size_t)(h0 + r) * 32 + tx];
    }
    __syncthreads();
#pragma unroll
    for (int hh = ty; hh < 32; hh += 8) {
        float acc = s_k[hh][tx];
#pragma unroll
        for (int r = 0; r < 32; r++) acc += s_a[hh][r] * s_b[r][tx];
        s_o[hh][tx] = acc;
    }
    __syncthreads();
#pragma unroll
    for (int ff = ty; ff < 32; ff += 8) {
        g_WT[(size_t)(f0 + ff) * H_DIM + h0 + tx] = __float2half_rn(s_o[tx][ff]);
    }
}

// ---------------------------------------------------------------------------
// Kernel 3: fp16 mma.sync GEMM, ldmatrix.x4, 512 threads.
// CTA 256x128, 16 warps 4(M)x4(N), warp tile 64x32, BK=64, 4-stage cp.async.
// Swizzle: byte ^ ((row&7)<<4).
// ---------------------------------------------------------------------------
__global__ __launch_bounds__(512, 1)
void gemm_kernel(const float* __restrict__ bias, float* __restrict__ out) {
    extern __shared__ char smem[];
    const uint32_t sb = smem_u32(smem);
    const int tid = threadIdx.x;
    const int wid = tid >> 5, lane = tid & 31;
    const int l2 = lane >> 2, l3 = lane & 3;
    const int mwarp = (wid >> 2) * 64;
    const int nwarp = (wid & 3) * 32;

    const int mt = blockIdx.x & 31;           // M fast => A reuse within wave
    const int nt = blockIdx.x >> 5;
    const size_t m0 = (size_t)mt * BM, n0 = (size_t)nt * BN;
    const __half* Ap = g_Y + m0 * H_DIM;
    const __half* Bp = g_WT + n0 * H_DIM;

    auto load_chunk = [&](int j, int stage) {
        const uint32_t st = sb + stage * STAGE_BYTES;
        const __half* a = Ap + j * BK;
#pragma unroll
        for (int i = 0; i < 4; i++) {
            int g = tid + i * 512;
            int row = g >> 3, c = g & 7;
            uint32_t off = (uint32_t)row * 128 +
                           (((uint32_t)c * 16) ^ (((uint32_t)row & 7) << 4));
            cp16(st + off, a + (size_t)row * H_DIM + c * 8);
        }
        const __half* b = Bp + j * BK;
        const uint32_t stb = st + A_STAGE_BYTES;
#pragma unroll
        for (int i = 0; i < 2; i++) {
            int g = tid + i * 512;
            int row = g >> 3, c = g & 7;
            uint32_t off = (uint32_t)row * 128 +
                           (((uint32_t)c * 16) ^ (((uint32_t)row & 7) << 4));
            cp16(stb + off, b + (size_t)row * H_DIM + c * 8);
        }
        asm volatile("cp.async.commit_group;" ::: "memory");
    };

    float acc[4][4][4];
#pragma unroll
    for (int mi = 0; mi < 4; mi++)
#pragma unroll
        for (int ni = 0; ni < 4; ni++)
#pragma unroll
            for (int q = 0; q < 4; q++) acc[mi][ni][q] = 0.f;

    load_chunk(0, 0);
    load_chunk(1, 1);
    load_chunk(2, 2);

    // ldmatrix lane addressing (swizzle row depends on lane&7)
    const uint32_t aRowB = (uint32_t)(mwarp + (lane & 15)) * 128;
    const uint32_t aSel  = ((uint32_t)(lane >> 4)) << 4;       // 0 / 16 bytes
    const uint32_t bRowB = (uint32_t)(nwarp + (lane & 7) + ((lane >> 4) << 3)) * 128;
    const uint32_t bSel  = ((uint32_t)((lane >> 3) & 1)) << 4;
    const uint32_t swzA  = ((uint32_t)(lane & 7)) << 4;

    for (int j = 0; j < NCHUNK; j++) {
        const int stage = j & 3;
        asm volatile("cp.async.wait_group 2;" ::: "memory");
        __syncthreads();

        if (j + 3 < NCHUNK) load_chunk(j + 3, (j + 3) & 3);
        else asm volatile("cp.async.commit_group;" ::: "memory");

        const uint32_t stA = sb + stage * STAGE_BYTES;
        const uint32_t stB = stA + A_STAGE_BYTES;
#pragma unroll
        for (int ks = 0; ks < 4; ks++) {
            const uint32_t kaoff = (((uint32_t)ks * 32 + aSel) ^ swzA);
            const uint32_t kboff = (((uint32_t)ks * 32 + bSel) ^ swzA);
            uint32_t af[4][4];
#pragma unroll
            for (int mi = 0; mi < 4; mi++)
                ldsm_x4(af[mi], stA + aRowB + (uint32_t)mi * 2048 + kaoff);
            uint32_t bf[2][4];
#pragma unroll
            for (int p = 0; p < 2; p++)
                ldsm_x4(bf[p], stB + bRowB + (uint32_t)p * 2048 + kboff);
#pragma unroll
            for (int mi = 0; mi < 4; mi++)
#pragma unroll
                for (int p = 0; p < 2; p++) {
                    mma_f16(acc[mi][2 * p],     af[mi][0], af[mi][1],
                            af[mi][2], af[mi][3], bf[p][0], bf[p][1]);
                    mma_f16(acc[mi][2 * p + 1], af[mi][0], af[mi][1],
                            af[mi][2], af[mi][3], bf[p][2], bf[p][3]);
                }
        }
    }

    // ---- epilogue: direct gmem stores, 32B-aligned float2 segments ----
    const float* bptr = bias + n0 + nwarp + 2 * l3;
#pragma unroll
    for (int ni = 0; ni < 4; ni++) {
        float bv0 = __ldg(bptr + ni * 8);
        float bv1 = __ldg(bptr + ni * 8 + 1);
        size_t gn = n0 + nwarp + (size_t)ni * 8 + 2 * l3;
#pragma unroll
        for (int mi = 0; mi < 4; mi++) {
            size_t gm = m0 + mwarp + (size_t)mi * 16 + l2;
            float2 v0 = make_float2(acc[mi][ni][0] + bv0, acc[mi][ni][1] + bv1);
            float2 v1 = make_float2(acc[mi][ni][2] + bv0, acc[mi][ni][3] + bv1);
            *reinterpret_cast<float2*>(out + gm * F_DIM + gn) = v0;
            *reinterpret_cast<float2*>(out + (gm + 8) * F_DIM + gn) = v1;
        }
    }
}

// ---------------------------------------------------------------------------
extern "C" void kernel_launch(void* const* d_in, const int* in_sizes, int n_in,
                              void* d_out, int out_size) {
    (void)in_sizes; (void)n_in; (void)out_size;
    const float* x       = (const float*)d_in[0];
    const float* scale   = (const float*)d_in[1];
    const float* ln_bias = (const float*)d_in[2];
    const float* kern    = (const float*)d_in[3];
    const float* la      = (const float*)d_in[4];
    const float* lb      = (const float*)d_in[5];
    const float* bias    = (const float*)d_in[6];
    float* out = (float*)d_out;

    cudaFuncSetAttribute(gemm_kernel,
                         cudaFuncAttributeMaxDynamicSharedMemorySize, GEMM_SMEM);

    ln_kernel<<<M_DIM, 256>>>(x, scale, ln_bias);
    weff_kernel<<<dim3(F_DIM / 32, H_DIM / 32), dim3(32, 8)>>>(kern, la, lb);
    gemm_kernel<<<(M_DIM / BM) * (F_DIM / BN), 512, GEMM_SMEM>>>(bias, out);
}

// round 8
// speedup vs baseline: 2.0457x; 1.0325x over previous
#include <cuda_runtime.h>
#include <cuda_fp16.h>
#include <cstdint>

// ---------------------------------------------------------------------------
// LayerNormDenseGeneral: out = LN(x) @ (kernel + lora_a@lora_b) + bias
// M=8192, K=H=4096, N=F=4096, R=32
// compute_103 build (no tcgen05). fp16 mma.sync m16n8k16 + ldmatrix.x4.
// R8: fix R7 retile bug (warp M-tile is 64 rows -> mi loop must cover 4
// 16-row tiles; R7 only did 2, leaving half the rows unwritten).
// 128x128 CTA, 3-stage 96KB smem, 2 CTAs/SM for barrier overlap.
// ---------------------------------------------------------------------------

#define H_DIM 4096
#define F_DIM 4096
#define M_DIM 8192

#define BM 128
#define BN 128
#define BK 64                                // K elements per chunk (128 B fp16)
#define NCHUNK (H_DIM / BK)                  // 64
#define A_STAGE_BYTES (BM * BK * 2)          // 16384
#define B_STAGE_BYTES (BN * BK * 2)          // 16384
#define STAGE_BYTES (A_STAGE_BYTES + B_STAGE_BYTES)   // 32768
#define NSTAGE 3
#define GEMM_SMEM (NSTAGE * STAGE_BYTES)     // 98304

__device__ __align__(16) __half g_Y[(size_t)M_DIM * H_DIM];   // LN(x), fp16
__device__ __align__(16) __half g_WT[(size_t)F_DIM * H_DIM];  // W_eff^T, fp16

// ---------------------------------------------------------------------------
__device__ __forceinline__ uint32_t smem_u32(const void* p) {
    uint32_t a;
    asm("{ .reg .u64 t; cvta.to.shared.u64 t, %1; cvt.u32.u64 %0, t; }"
        : "=r"(a) : "l"(p));
    return a;
}

__device__ __forceinline__ void cp16(uint32_t dst, const void* src) {
    uint64_t g = __cvta_generic_to_global(src);
    asm volatile("cp.async.cg.shared.global [%0], [%1], 16;"
                 :: "r"(dst), "l"(g) : "memory");
}

__device__ __forceinline__ void ldsm_x4(uint32_t* r, uint32_t addr) {
    asm volatile("ldmatrix.sync.aligned.m8n8.x4.shared.b16 {%0,%1,%2,%3}, [%4];"
                 : "=r"(r[0]), "=r"(r[1]), "=r"(r[2]), "=r"(r[3]) : "r"(addr));
}

__device__ __forceinline__ uint32_t packh2(float lo, float hi) {
    __half2 h = __floats2half2_rn(lo, hi);
    return *reinterpret_cast<uint32_t*>(&h);
}

__device__ __forceinline__ void mma_f16(float* d,
                                        uint32_t a0, uint32_t a1,
                                        uint32_t a2, uint32_t a3,
                                        uint32_t b0, uint32_t b1) {
    asm volatile(
        "mma.sync.aligned.m16n8k16.row.col.f32.f16.f16.f32 "
        "{%0,%1,%2,%3}, {%4,%5,%6,%7}, {%8,%9}, {%0,%1,%2,%3};"
        : "+f"(d[0]), "+f"(d[1]), "+f"(d[2]), "+f"(d[3])
        : "r"(a0), "r"(a1), "r"(a2), "r"(a3), "r"(b0), "r"(b1));
}

// ---------------------------------------------------------------------------
// Kernel 1: LayerNorm rows of x -> g_Y (fp16)
// ---------------------------------------------------------------------------
__global__ __launch_bounds__(256, 1)
void ln_kernel(const float* __restrict__ x, const float* __restrict__ gamma,
               const float* __restrict__ beta) {
    __shared__ float sm[8];
    int row = blockIdx.x;
    const float4* xr = reinterpret_cast<const float4*>(x) + (size_t)row * (H_DIM / 4);
    float4 v[4];
    float s = 0.f;
#pragma unroll
    for (int i = 0; i < 4; i++) {
        v[i] = xr[threadIdx.x + i * 256];
        s += (v[i].x + v[i].y) + (v[i].z + v[i].w);
    }
#pragma unroll
    for (int o = 16; o > 0; o >>= 1) s += __shfl_xor_sync(0xffffffffu, s, o);
    if ((threadIdx.x & 31) == 0) sm[threadIdx.x >> 5] = s;
    __syncthreads();
    float tot = 0.f;
#pragma unroll
    for (int k = 0; k < 8; k++) tot += sm[k];
    float mean = tot * (1.0f / H_DIM);
    __syncthreads();

    float s2 = 0.f;
#pragma unroll
    for (int i = 0; i < 4; i++) {
        float a = v[i].x - mean, b = v[i].y - mean;
        float c = v[i].z - mean, d = v[i].w - mean;
        s2 += (a * a + b * b) + (c * c + d * d);
    }
#pragma unroll
    for (int o = 16; o > 0; o >>= 1) s2 += __shfl_xor_sync(0xffffffffu, s2, o);
    if ((threadIdx.x & 31) == 0) sm[threadIdx.x >> 5] = s2;
    __syncthreads();
    float t2 = 0.f;
#pragma unroll
    for (int k = 0; k < 8; k++) t2 += sm[k];
    float rstd = rsqrtf(t2 * (1.0f / H_DIM) + 1e-6f);

    const float4* g4 = reinterpret_cast<const float4*>(gamma);
    const float4* b4 = reinterpret_cast<const float4*>(beta);
    uint2* yr = reinterpret_cast<uint2*>(g_Y + (size_t)row * H_DIM);
#pragma unroll
    for (int i = 0; i < 4; i++) {
        int idx = threadIdx.x + i * 256;
        float4 g = g4[idx], bb = b4[idx];
        float o0 = (v[i].x - mean) * rstd * g.x + bb.x;
        float o1 = (v[i].y - mean) * rstd * g.y + bb.y;
        float o2 = (v[i].z - mean) * rstd * g.z + bb.z;
        float o3 = (v[i].w - mean) * rstd * g.w + bb.w;
        yr[idx] = make_uint2(packh2(o0, o1), packh2(o2, o3));
    }
}

// ---------------------------------------------------------------------------
// Kernel 2: g_WT[f][h] = fp16( kernel[h][f] + lora_a[h][:]@lora_b[:][f] )
// ---------------------------------------------------------------------------
__global__ __launch_bounds__(256, 1)
void weff_kernel(const float* __restrict__ Wk, const float* __restrict__ La,
                 const float* __restrict__ Lb) {
    __shared__ float s_k[32][33], s_a[32][33], s_b[32][33], s_o[32][33];
    int tx = threadIdx.x, ty = threadIdx.y;
    int f0 = blockIdx.x * 32, h0 = blockIdx.y * 32;
#pragma unroll
    for (int r = ty; r < 32; r += 8) {
        s_k[r][tx] = Wk[(size_t)(h0 + r) * F_DIM + f0 + tx];
        s_b[r][tx] = Lb[(size_t)r * F_DIM + f0 + tx];
        s_a[r][tx] = La[(size_t)(h0 + r) * 32 + tx];
    }
    __syncthreads();
#pragma unroll
    for (int hh = ty; hh < 32; hh += 8) {
        float acc = s_k[hh][tx];
#pragma unroll
        for (int r = 0; r < 32; r++) acc += s_a[hh][r] * s_b[r][tx];
        s_o[hh][tx] = acc;
    }
    __syncthreads();
#pragma unroll
    for (int ff = ty; ff < 32; ff += 8) {
        g_WT[(size_t)(f0 + ff) * H_DIM + h0 + tx] = __float2half_rn(s_o[tx][ff]);
    }
}

// ---------------------------------------------------------------------------
// Kernel 3: fp16 mma.sync GEMM, ldmatrix.x4, 256 threads, 2 CTAs/SM.
// CTA 128x128, 8 warps 2(M)x4(N), warp tile 64x32 (mi=0..3), BK=64,
// 3-stage cp.async. Swizzle: byte ^ ((row&7)<<4).
// ---------------------------------------------------------------------------
__global__ __launch_bounds__(256, 2)
void gemm_kernel(const float* __restrict__ bias, float* __restrict__ out) {
    extern __shared__ char smem[];
    const uint32_t sb = smem_u32(smem);
    const int tid = threadIdx.x;
    const int wid = tid >> 5, lane = tid & 31;
    const int l2 = lane >> 2, l3 = lane & 3;
    const int mwarp = (wid >> 2) * 64;
    const int nwarp = (wid & 3) * 32;

    // supertile: groups of 8 M-tiles x 32 N-tiles (mt fast within group)
    const int r = blockIdx.x & 255;           // 8*32 - 1
    const int g = blockIdx.x >> 8;
    const int mt = g * 8 + (r & 7);
    const int nt = r >> 3;
    const size_t m0 = (size_t)mt * BM, n0 = (size_t)nt * BN;
    const __half* Ap = g_Y + m0 * H_DIM;
    const __half* Bp = g_WT + n0 * H_DIM;

    auto load_chunk = [&](int j, int stage) {
        const uint32_t st = sb + stage * STAGE_BYTES;
        const __half* a = Ap + j * BK;
#pragma unroll
        for (int i = 0; i < 4; i++) {
            int gg = tid + i * 256;
            int row = gg >> 3, c = gg & 7;
            uint32_t off = (uint32_t)row * 128 +
                           (((uint32_t)c * 16) ^ (((uint32_t)row & 7) << 4));
            cp16(st + off, a + (size_t)row * H_DIM + c * 8);
        }
        const __half* b = Bp + j * BK;
        const uint32_t stb = st + A_STAGE_BYTES;
#pragma unroll
        for (int i = 0; i < 4; i++) {
            int gg = tid + i * 256;
            int row = gg >> 3, c = gg & 7;
            uint32_t off = (uint32_t)row * 128 +
                           (((uint32_t)c * 16) ^ (((uint32_t)row & 7) << 4));
            cp16(stb + off, b + (size_t)row * H_DIM + c * 8);
        }
        asm volatile("cp.async.commit_group;" ::: "memory");
    };

    float acc[4][4][4];
#pragma unroll
    for (int mi = 0; mi < 4; mi++)
#pragma unroll
        for (int ni = 0; ni < 4; ni++)
#pragma unroll
            for (int q = 0; q < 4; q++) acc[mi][ni][q] = 0.f;

    load_chunk(0, 0);
    load_chunk(1, 1);

    // ldmatrix lane addressing (swizzle row depends on lane&7)
    const uint32_t aRowB = (uint32_t)(mwarp + (lane & 15)) * 128;
    const uint32_t aSel  = ((uint32_t)(lane >> 4)) << 4;       // 0 / 16 bytes
    const uint32_t bRowB = (uint32_t)(nwarp + (lane & 7) + ((lane >> 4) << 3)) * 128;
    const uint32_t bSel  = ((uint32_t)((lane >> 3) & 1)) << 4;
    const uint32_t swzA  = ((uint32_t)(lane & 7)) << 4;

    int stage = 0;
    for (int j = 0; j < NCHUNK; j++) {
        asm volatile("cp.async.wait_group 1;" ::: "memory");
        __syncthreads();

        if (j + 2 < NCHUNK) {
            int s2 = stage + 2; if (s2 >= NSTAGE) s2 -= NSTAGE;
            load_chunk(j + 2, s2);
        } else {
            asm volatile("cp.async.commit_group;" ::: "memory");
        }

        const uint32_t stA = sb + stage * STAGE_BYTES;
        const uint32_t stB = stA + A_STAGE_BYTES;
#pragma unroll
        for (int ks = 0; ks < 4; ks++) {
            const uint32_t kaoff = (((uint32_t)ks * 32 + aSel) ^ swzA);
            const uint32_t kboff = (((uint32_t)ks * 32 + bSel) ^ swzA);
            uint32_t af[4][4];
#pragma unroll
            for (int mi = 0; mi < 4; mi++)
                ldsm_x4(af[mi], stA + aRowB + (uint32_t)mi * 2048 + kaoff);
            uint32_t bf[2][4];
#pragma unroll
            for (int p = 0; p < 2; p++)
                ldsm_x4(bf[p], stB + bRowB + (uint32_t)p * 2048 + kboff);
#pragma unroll
            for (int mi = 0; mi < 4; mi++)
#pragma unroll
                for (int p = 0; p < 2; p++) {
                    mma_f16(acc[mi][2 * p],     af[mi][0], af[mi][1],
                            af[mi][2], af[mi][3], bf[p][0], bf[p][1]);
                    mma_f16(acc[mi][2 * p + 1], af[mi][0], af[mi][1],
                            af[mi][2], af[mi][3], bf[p][2], bf[p][3]);
                }
        }
        if (++stage == NSTAGE) stage = 0;
    }

    // ---- epilogue: direct gmem stores, 32B-aligned float2 segments ----
    const float* bptr = bias + n0 + nwarp + 2 * l3;
#pragma unroll
    for (int ni = 0; ni < 4; ni++) {
        float bv0 = __ldg(bptr + ni * 8);
        float bv1 = __ldg(bptr + ni * 8 + 1);
        size_t gn = n0 + nwarp + (size_t)ni * 8 + 2 * l3;
#pragma unroll
        for (int mi = 0; mi < 4; mi++) {
            size_t gm = m0 + mwarp + (size_t)mi * 16 + l2;
            float2 v0 = make_float2(acc[mi][ni][0] + bv0, acc[mi][ni][1] + bv1);
            float2 v1 = make_float2(acc[mi][ni][2] + bv0, acc[mi][ni][3] + bv1);
            *reinterpret_cast<float2*>(out + gm * F_DIM + gn) = v0;
            *reinterpret_cast<float2*>(out + (gm + 8) * F_DIM + gn) = v1;
        }
    }
}

// ---------------------------------------------------------------------------
extern "C" void kernel_launch(void* const* d_in, const int* in_sizes, int n_in,
                              void* d_out, int out_size) {
    (void)in_sizes; (void)n_in; (void)out_size;
    const float* x       = (const float*)d_in[0];
    const float* scale   = (const float*)d_in[1];
    const float* ln_bias = (const float*)d_in[2];
    const float* kern    = (const float*)d_in[3];
    const float* la      = (const float*)d_in[4];
    const float* lb      = (const float*)d_in[5];
    const float* bias    = (const float*)d_in[6];
    float* out = (float*)d_out;

    cudaFuncSetAttribute(gemm_kernel,
                         cudaFuncAttributeMaxDynamicSharedMemorySize, GEMM_SMEM);

    ln_kernel<<<M_DIM, 256>>>(x, scale, ln_bias);
    weff_kernel<<<dim3(F_DIM / 32, H_DIM / 32), dim3(32, 8)>>>(kern, la, lb);
    gemm_kernel<<<(M_DIM / BM) * (F_DIM / BN), 256, GEMM_SMEM>>>(bias, out);
}